// round 1
// baseline (speedup 1.0000x reference)
#include <cuda_runtime.h>
#include <math.h>

// Problem constants
#define BATCH 4
#define SEQ   4096
#define DIM   128
#define TOK   (BATCH*SEQ)   // 16384

// GEMM tiling
#define BM 128
#define BN 128
#define PAD 132   // padded row length for k-major [k][row] smem tiles (132 = 4-float pad)

// ---------------- device scratch (allocation-free: __device__ globals) -------
__device__ float g_Q[TOK*DIM];
__device__ float g_K[TOK*DIM];
__device__ float g_V[TOK*DIM];
__device__ float g_S[BATCH*SEQ];                 // row sums of exp(scores)
__device__ float g_C[BATCH*SEQ];                 // column weights (already /N)
__device__ float g_E[(size_t)BATCH*SEQ*SEQ];     // exp(scores), 268 MB

// ---------------- zero accumulators + output --------------------------------
__global__ void zero_kernel(float* out) {
    int i = blockIdx.x * blockDim.x + threadIdx.x;
    if (i < BATCH*SEQ) { g_S[i] = 0.0f; g_C[i] = 0.0f; }
    if (i < BATCH*DIM) out[i] = 0.0f;
}

// ---------------- K1: QKV projection  y = x @ W^T + b ------------------------
// One GEMM per blockIdx.z (0:Q, 1:K, 2:V). M=16384 (rows), N=128 (=DIM), K=128.
__global__ __launch_bounds__(256, 1)
void proj_kernel(const float* __restrict__ x,
                 const float* __restrict__ Wq, const float* __restrict__ bq,
                 const float* __restrict__ Wk, const float* __restrict__ bk,
                 const float* __restrict__ Wv, const float* __restrict__ bv) {
    extern __shared__ float sm[];
    float* As = sm;             // [DIM][PAD]  As[k*PAD + row]
    float* Ws = sm + DIM*PAD;   // [DIM][PAD]  Ws[d*PAD + e]  (W transposed)

    const float* W; const float* bias; float* out;
    if (blockIdx.z == 0)      { W = Wq; bias = bq; out = g_Q; }
    else if (blockIdx.z == 1) { W = Wk; bias = bk; out = g_K; }
    else                      { W = Wv; bias = bv; out = g_V; }

    const int rowBase = blockIdx.y * BM;
    const int tid = threadIdx.x;

    // load x tile [BM x DIM] transposed into As[k][row]
    for (int i = tid; i < BM*DIM; i += 256) {
        int r = i >> 7, k = i & 127;
        As[k*PAD + r] = x[(size_t)(rowBase + r)*DIM + k];
    }
    // load W [e][d] transposed into Ws[d][e]
    for (int i = tid; i < DIM*DIM; i += 256) {
        int e = i >> 7, d = i & 127;
        Ws[d*PAD + e] = W[i];
    }
    __syncthreads();

    const int tx = tid & 15, ty = tid >> 4;
    float acc[8][8];
    #pragma unroll
    for (int i = 0; i < 8; i++)
        #pragma unroll
        for (int j = 0; j < 8; j++) acc[i][j] = 0.0f;

    #pragma unroll 4
    for (int k = 0; k < DIM; ++k) {
        float4 a0 = *(const float4*)(As + k*PAD + ty*8);
        float4 a1 = *(const float4*)(As + k*PAD + ty*8 + 4);
        float4 b0 = *(const float4*)(Ws + k*PAD + tx*8);
        float4 b1 = *(const float4*)(Ws + k*PAD + tx*8 + 4);
        float a[8] = {a0.x,a0.y,a0.z,a0.w,a1.x,a1.y,a1.z,a1.w};
        float b[8] = {b0.x,b0.y,b0.z,b0.w,b1.x,b1.y,b1.z,b1.w};
        #pragma unroll
        for (int i = 0; i < 8; i++)
            #pragma unroll
            for (int j = 0; j < 8; j++) acc[i][j] += a[i]*b[j];
    }

    #pragma unroll
    for (int i = 0; i < 8; i++) {
        int r = rowBase + ty*8 + i;
        float4 o0, o1;
        o0.x = acc[i][0] + __ldg(&bias[tx*8+0]);
        o0.y = acc[i][1] + __ldg(&bias[tx*8+1]);
        o0.z = acc[i][2] + __ldg(&bias[tx*8+2]);
        o0.w = acc[i][3] + __ldg(&bias[tx*8+3]);
        o1.x = acc[i][4] + __ldg(&bias[tx*8+4]);
        o1.y = acc[i][5] + __ldg(&bias[tx*8+5]);
        o1.z = acc[i][6] + __ldg(&bias[tx*8+6]);
        o1.w = acc[i][7] + __ldg(&bias[tx*8+7]);
        *(float4*)(out + (size_t)r*DIM + tx*8)     = o0;
        *(float4*)(out + (size_t)r*DIM + tx*8 + 4) = o1;
    }
}

// ---------------- K2: E = exp(Q @ K^T), rowsums S ----------------------------
__global__ __launch_bounds__(256, 1)
void score_kernel() {
    extern __shared__ float sm[];
    float* Qs = sm;             // [DIM][PAD]
    float* Ks = sm + DIM*PAD;   // [DIM][PAD]

    const int b = blockIdx.z;
    const int rowBase = blockIdx.y * BM;
    const int colBase = blockIdx.x * BN;
    const float* Qp = g_Q + (size_t)b*SEQ*DIM;
    const float* Kp = g_K + (size_t)b*SEQ*DIM;
    const int tid = threadIdx.x;

    for (int i = tid; i < BM*DIM; i += 256) {
        int r = i >> 7, k = i & 127;
        Qs[k*PAD + r] = Qp[(size_t)(rowBase + r)*DIM + k];
    }
    for (int i = tid; i < BN*DIM; i += 256) {
        int c = i >> 7, k = i & 127;
        Ks[k*PAD + c] = Kp[(size_t)(colBase + c)*DIM + k];
    }
    __syncthreads();

    const int tx = tid & 15, ty = tid >> 4;
    float acc[8][8];
    #pragma unroll
    for (int i = 0; i < 8; i++)
        #pragma unroll
        for (int j = 0; j < 8; j++) acc[i][j] = 0.0f;

    #pragma unroll 4
    for (int k = 0; k < DIM; ++k) {
        float4 a0 = *(const float4*)(Qs + k*PAD + ty*8);
        float4 a1 = *(const float4*)(Qs + k*PAD + ty*8 + 4);
        float4 b0 = *(const float4*)(Ks + k*PAD + tx*8);
        float4 b1 = *(const float4*)(Ks + k*PAD + tx*8 + 4);
        float a[8] = {a0.x,a0.y,a0.z,a0.w,a1.x,a1.y,a1.z,a1.w};
        float bb[8] = {b0.x,b0.y,b0.z,b0.w,b1.x,b1.y,b1.z,b1.w};
        #pragma unroll
        for (int i = 0; i < 8; i++)
            #pragma unroll
            for (int j = 0; j < 8; j++) acc[i][j] += a[i]*bb[j];
    }

    // epilogue: exp, store E, reduce row-partial sums
    #pragma unroll
    for (int i = 0; i < 8; i++) {
        int r = rowBase + ty*8 + i;
        float e[8]; float rs = 0.0f;
        #pragma unroll
        for (int j = 0; j < 8; j++) { e[j] = __expf(acc[i][j]); rs += e[j]; }
        size_t base = ((size_t)b*SEQ + r)*SEQ + colBase + tx*8;
        *(float4*)(g_E + base)     = make_float4(e[0],e[1],e[2],e[3]);
        *(float4*)(g_E + base + 4) = make_float4(e[4],e[5],e[6],e[7]);
        // reduce over the 16 tx lanes sharing this row (xor<16 stays in half-warp)
        #pragma unroll
        for (int o = 8; o; o >>= 1) rs += __shfl_xor_sync(0xffffffffu, rs, o);
        if (tx == 0) atomicAdd(&g_S[b*SEQ + r], rs);
    }
}

// ---------------- K3: c[m] = (1/N) * sum_n E[n,m]/S[n] -----------------------
#define K3_ROWS 1024
__global__ __launch_bounds__(256, 4)
void colsum_kernel() {
    __shared__ float invS[K3_ROWS];
    const int b = blockIdx.z;
    const int mBase = blockIdx.x * 256;
    const int nBase = blockIdx.y * K3_ROWS;
    const int tid = threadIdx.x;

    for (int i = tid; i < K3_ROWS; i += 256)
        invS[i] = 1.0f / g_S[b*SEQ + nBase + i];
    __syncthreads();

    const int m = mBase + tid;
    const float* Ep = g_E + ((size_t)b*SEQ + nBase)*SEQ + m;
    float a0 = 0.f, a1 = 0.f, a2 = 0.f, a3 = 0.f;
    #pragma unroll 2
    for (int n = 0; n < K3_ROWS; n += 4) {
        a0 += Ep[(size_t)(n+0)*SEQ] * invS[n+0];
        a1 += Ep[(size_t)(n+1)*SEQ] * invS[n+1];
        a2 += Ep[(size_t)(n+2)*SEQ] * invS[n+2];
        a3 += Ep[(size_t)(n+3)*SEQ] * invS[n+3];
    }
    atomicAdd(&g_C[b*SEQ + m], (a0+a1+a2+a3) * (1.0f/SEQ));
}

// ---------------- K4: out[b,d] = sum_m c[m] * V[b,m,d] -----------------------
#define K4_CHUNK (SEQ/8)   // 512 rows per block
__global__ __launch_bounds__(128, 8)
void out_kernel(float* __restrict__ out) {
    const int b = blockIdx.y;
    const int mBase = blockIdx.x * K4_CHUNK;
    const int d = threadIdx.x;
    const float* Vp = g_V + ((size_t)b*SEQ + mBase)*DIM + d;
    const float* Cp = g_C + b*SEQ + mBase;
    float acc = 0.0f;
    #pragma unroll 4
    for (int m = 0; m < K4_CHUNK; m++)
        acc += Cp[m] * Vp[(size_t)m*DIM];
    atomicAdd(&out[b*DIM + d], acc);
}

// ---------------- launch -----------------------------------------------------
extern "C" void kernel_launch(void* const* d_in, const int* in_sizes, int n_in,
                              void* d_out, int out_size) {
    const float* x  = (const float*)d_in[0];
    const float* Wq = (const float*)d_in[1];
    const float* bq = (const float*)d_in[2];
    const float* Wk = (const float*)d_in[3];
    const float* bk = (const float*)d_in[4];
    const float* Wv = (const float*)d_in[5];
    const float* bv = (const float*)d_in[6];
    float* out = (float*)d_out;

    const int smem = 2 * DIM * PAD * sizeof(float);   // 135168 bytes
    cudaFuncSetAttribute(proj_kernel,  cudaFuncAttributeMaxDynamicSharedMemorySize, smem);
    cudaFuncSetAttribute(score_kernel, cudaFuncAttributeMaxDynamicSharedMemorySize, smem);

    zero_kernel<<<(BATCH*SEQ + 255)/256, 256>>>(out);

    dim3 gProj(1, TOK/BM, 3);
    proj_kernel<<<gProj, 256, smem>>>(x, Wq, bq, Wk, bk, Wv, bv);

    dim3 gScore(SEQ/BN, SEQ/BM, BATCH);   // 32 x 32 x 4
    score_kernel<<<gScore, 256, smem>>>();

    dim3 gCol(SEQ/256, SEQ/K3_ROWS, BATCH);  // 16 x 4 x 4
    colsum_kernel<<<gCol, 256>>>();

    dim3 gOut(8, BATCH);
    out_kernel<<<gOut, 128>>>(out);
}

// round 3
// speedup vs baseline: 2.2985x; 2.2985x over previous
#include <cuda_runtime.h>
#include <cuda_bf16.h>
#include <math.h>
#include <stdint.h>

// Problem constants
#define BATCH 4
#define SEQ   4096
#define DIM   128
#define TOK   (BATCH*SEQ)   // 16384

// GEMM tiling
#define BM 128
#define BN 128
#define PADK 132   // padded row length (floats) for [row][k] smem tiles

// ---------------- device scratch (allocation-free: __device__ globals) -------
__device__ float g_Q[TOK*DIM];
__device__ float g_K[TOK*DIM];
__device__ float g_V[TOK*DIM];
__device__ float g_S[BATCH*SEQ];                       // row sums of exp(scores)
__device__ float g_C[BATCH*SEQ];                       // column weights (already /N)
__device__ __nv_bfloat16 g_E[(size_t)BATCH*SEQ*SEQ];   // exp(scores) in bf16, 134 MB

// ---------------- helpers ----------------------------------------------------
__device__ __forceinline__ float tf32_round(float x) {
    uint32_t u;
    asm("cvt.rna.tf32.f32 %0, %1;" : "=r"(u) : "f"(x));
    return __uint_as_float(u);
}

#define MMA_TF32(C, A, B)                                                     \
  asm volatile("mma.sync.aligned.m16n8k8.row.col.f32.tf32.tf32.f32 "          \
    "{%0,%1,%2,%3}, {%4,%5,%6,%7}, {%8,%9}, {%0,%1,%2,%3};"                   \
    : "+f"((C)[0]), "+f"((C)[1]), "+f"((C)[2]), "+f"((C)[3])                  \
    : "r"((A)[0]), "r"((A)[1]), "r"((A)[2]), "r"((A)[3]),                     \
      "r"((B)[0]), "r"((B)[1]))

// ---------------- zero accumulators + output --------------------------------
__global__ void zero_kernel(float* out) {
    int i = blockIdx.x * blockDim.x + threadIdx.x;
    if (i < BATCH*SEQ) { g_S[i] = 0.0f; g_C[i] = 0.0f; }
    if (i < BATCH*DIM) out[i] = 0.0f;
}

// ---------------- K1: QKV projection  y = x @ W^T + b  (tf32 mma) ------------
// One GEMM per blockIdx.z (0:Q, 1:K, 2:V). M=16384 rows, N=K=128.
__global__ __launch_bounds__(256, 1)
void proj_kernel(const float* __restrict__ x,
                 const float* __restrict__ Wq, const float* __restrict__ bq,
                 const float* __restrict__ Wk, const float* __restrict__ bk,
                 const float* __restrict__ Wv, const float* __restrict__ bv) {
    extern __shared__ float sm[];
    float* As = sm;              // [BM][PADK]  x tile, row-major [m][k]
    float* Bs = sm + BM*PADK;    // [BN][PADK]  W, row-major [e][k]

    const float* W; const float* bias; float* outp;
    if (blockIdx.z == 0)      { W = Wq; bias = bq; outp = g_Q; }
    else if (blockIdx.z == 1) { W = Wk; bias = bk; outp = g_K; }
    else                      { W = Wv; bias = bv; outp = g_V; }

    const int rowBase = blockIdx.y * BM;
    const int tid = threadIdx.x;

    // fill smem tiles (tf32-rounded)
    for (int i = tid*4; i < BM*DIM; i += 256*4) {
        int r = i >> 7, k = i & 127;
        float4 v = *(const float4*)(x + (size_t)(rowBase + r)*DIM + k);
        v.x = tf32_round(v.x); v.y = tf32_round(v.y);
        v.z = tf32_round(v.z); v.w = tf32_round(v.w);
        *(float4*)(As + r*PADK + k) = v;
        float4 w = *(const float4*)(W + i);
        w.x = tf32_round(w.x); w.y = tf32_round(w.y);
        w.z = tf32_round(w.z); w.w = tf32_round(w.w);
        *(float4*)(Bs + r*PADK + k) = w;
    }
    __syncthreads();

    const int lane = tid & 31, warp = tid >> 5;
    const int wm = (warp >> 1) * 32;   // 0..96
    const int wn = (warp & 1) * 64;    // 0,64
    const int g = lane >> 2, t = lane & 3;

    float c[2][8][4];
    #pragma unroll
    for (int mt = 0; mt < 2; mt++)
        #pragma unroll
        for (int nt = 0; nt < 8; nt++)
            #pragma unroll
            for (int j = 0; j < 4; j++) c[mt][nt][j] = 0.0f;

    #pragma unroll
    for (int kk = 0; kk < DIM/8; kk++) {
        const int kb = kk*8;
        uint32_t a[2][4], bb[8][2];
        #pragma unroll
        for (int mt = 0; mt < 2; mt++) {
            const float* p = As + (wm + mt*16 + g)*PADK + kb + t;
            a[mt][0] = __float_as_uint(p[0]);
            a[mt][1] = __float_as_uint(p[8*PADK]);
            a[mt][2] = __float_as_uint(p[4]);
            a[mt][3] = __float_as_uint(p[8*PADK + 4]);
        }
        #pragma unroll
        for (int nt = 0; nt < 8; nt++) {
            const float* p = Bs + (wn + nt*8 + g)*PADK + kb + t;
            bb[nt][0] = __float_as_uint(p[0]);
            bb[nt][1] = __float_as_uint(p[4]);
        }
        #pragma unroll
        for (int mt = 0; mt < 2; mt++)
            #pragma unroll
            for (int nt = 0; nt < 8; nt++)
                MMA_TF32(c[mt][nt], a[mt], bb[nt]);
    }

    // epilogue: add bias, store fp32
    #pragma unroll
    for (int mt = 0; mt < 2; mt++) {
        const int r0 = rowBase + wm + mt*16 + g;
        #pragma unroll
        for (int nt = 0; nt < 8; nt++) {
            const int cn = wn + nt*8 + 2*t;
            float b0 = __ldg(&bias[cn]), b1 = __ldg(&bias[cn+1]);
            float2 v0 = make_float2(c[mt][nt][0] + b0, c[mt][nt][1] + b1);
            float2 v1 = make_float2(c[mt][nt][2] + b0, c[mt][nt][3] + b1);
            *(float2*)(outp + (size_t)r0*DIM + cn)       = v0;
            *(float2*)(outp + (size_t)(r0+8)*DIM + cn)   = v1;
        }
    }
}

// ---------------- K2: E = exp(Q @ K^T) (bf16), rowsums S (tf32 mma) ----------
__global__ __launch_bounds__(256, 1)
void score_kernel() {
    extern __shared__ float sm[];
    float* Qs = sm;              // [BM][PADK]
    float* Ks = sm + BM*PADK;    // [BN][PADK]

    const int b = blockIdx.z;
    const int rowBase = blockIdx.y * BM;
    const int colBase = blockIdx.x * BN;
    const float* Qp = g_Q + (size_t)b*SEQ*DIM + (size_t)rowBase*DIM;
    const float* Kp = g_K + (size_t)b*SEQ*DIM + (size_t)colBase*DIM;
    const int tid = threadIdx.x;

    for (int i = tid*4; i < BM*DIM; i += 256*4) {
        int r = i >> 7, k = i & 127;
        float4 v = *(const float4*)(Qp + r*DIM + k);
        v.x = tf32_round(v.x); v.y = tf32_round(v.y);
        v.z = tf32_round(v.z); v.w = tf32_round(v.w);
        *(float4*)(Qs + r*PADK + k) = v;
        float4 w = *(const float4*)(Kp + r*DIM + k);
        w.x = tf32_round(w.x); w.y = tf32_round(w.y);
        w.z = tf32_round(w.z); w.w = tf32_round(w.w);
        *(float4*)(Ks + r*PADK + k) = w;
    }
    __syncthreads();

    const int lane = tid & 31, warp = tid >> 5;
    const int wm = (warp >> 1) * 32;
    const int wn = (warp & 1) * 64;
    const int g = lane >> 2, t = lane & 3;

    float c[2][8][4];
    #pragma unroll
    for (int mt = 0; mt < 2; mt++)
        #pragma unroll
        for (int nt = 0; nt < 8; nt++)
            #pragma unroll
            for (int j = 0; j < 4; j++) c[mt][nt][j] = 0.0f;

    #pragma unroll
    for (int kk = 0; kk < DIM/8; kk++) {
        const int kb = kk*8;
        uint32_t a[2][4], bb[8][2];
        #pragma unroll
        for (int mt = 0; mt < 2; mt++) {
            const float* p = Qs + (wm + mt*16 + g)*PADK + kb + t;
            a[mt][0] = __float_as_uint(p[0]);
            a[mt][1] = __float_as_uint(p[8*PADK]);
            a[mt][2] = __float_as_uint(p[4]);
            a[mt][3] = __float_as_uint(p[8*PADK + 4]);
        }
        #pragma unroll
        for (int nt = 0; nt < 8; nt++) {
            const float* p = Ks + (wn + nt*8 + g)*PADK + kb + t;
            bb[nt][0] = __float_as_uint(p[0]);
            bb[nt][1] = __float_as_uint(p[4]);
        }
        #pragma unroll
        for (int mt = 0; mt < 2; mt++)
            #pragma unroll
            for (int nt = 0; nt < 8; nt++)
                MMA_TF32(c[mt][nt], a[mt], bb[nt]);
    }

    // epilogue: exp, store bf16 E, reduce row sums
    #pragma unroll
    for (int mt = 0; mt < 2; mt++) {
        const int r0 = rowBase + wm + mt*16 + g;
        const int r1 = r0 + 8;
        float rs0 = 0.0f, rs1 = 0.0f;
        #pragma unroll
        for (int nt = 0; nt < 8; nt++) {
            const int cn = colBase + wn + nt*8 + 2*t;
            float e0 = __expf(c[mt][nt][0]);
            float e1 = __expf(c[mt][nt][1]);
            float e2 = __expf(c[mt][nt][2]);
            float e3 = __expf(c[mt][nt][3]);
            rs0 += e0 + e1;
            rs1 += e2 + e3;
            size_t base0 = ((size_t)b*SEQ + r0)*SEQ + cn;
            size_t base1 = ((size_t)b*SEQ + r1)*SEQ + cn;
            *(__nv_bfloat162*)(g_E + base0) = __floats2bfloat162_rn(e0, e1);
            *(__nv_bfloat162*)(g_E + base1) = __floats2bfloat162_rn(e2, e3);
        }
        // reduce across the 4 t-lanes sharing each row
        #pragma unroll
        for (int o = 1; o <= 2; o <<= 1) {
            rs0 += __shfl_xor_sync(0xffffffffu, rs0, o);
            rs1 += __shfl_xor_sync(0xffffffffu, rs1, o);
        }
        if (t == 0) {
            atomicAdd(&g_S[b*SEQ + r0], rs0);
            atomicAdd(&g_S[b*SEQ + r1], rs1);
        }
    }
}

// ---------------- K3: c[m] = (1/N) * sum_n E[n,m]/S[n] -----------------------
#define K3_ROWS 256
__global__ __launch_bounds__(256, 8)
void colsum_kernel() {
    __shared__ float invS[K3_ROWS];
    const int b = blockIdx.z;
    const int mBase = blockIdx.x * 512;          // 512 m's per block (2 per thread)
    const int nBase = blockIdx.y * K3_ROWS;
    const int tid = threadIdx.x;

    if (tid < K3_ROWS) invS[tid] = 1.0f / g_S[b*SEQ + nBase + tid];
    __syncthreads();

    const __nv_bfloat162* Ep =
        (const __nv_bfloat162*)(g_E + ((size_t)b*SEQ + nBase)*SEQ) + (mBase >> 1) + tid;
    const size_t strideV2 = SEQ / 2;

    float a0 = 0.f, a1 = 0.f, b0 = 0.f, b1 = 0.f;
    #pragma unroll 8
    for (int n = 0; n < K3_ROWS; n += 2) {
        float2 v0 = __bfloat1622float2(Ep[(size_t)n * strideV2]);
        float2 v1 = __bfloat1622float2(Ep[(size_t)(n+1) * strideV2]);
        a0 += v0.x * invS[n];   a1 += v0.y * invS[n];
        b0 += v1.x * invS[n+1]; b1 += v1.y * invS[n+1];
    }
    const int m = mBase + tid*2;
    atomicAdd(&g_C[b*SEQ + m],     (a0 + b0) * (1.0f/SEQ));
    atomicAdd(&g_C[b*SEQ + m + 1], (a1 + b1) * (1.0f/SEQ));
}

// ---------------- K4: out[b,d] = sum_m c[m] * V[b,m,d] -----------------------
#define K4_CHUNK (SEQ/16)   // 256 rows per block
__global__ __launch_bounds__(128, 8)
void out_kernel(float* __restrict__ out) {
    const int b = blockIdx.y;
    const int mBase = blockIdx.x * K4_CHUNK;
    const int d = threadIdx.x;
    const float* Vp = g_V + ((size_t)b*SEQ + mBase)*DIM + d;
    const float* Cp = g_C + b*SEQ + mBase;
    float acc = 0.0f;
    #pragma unroll 8
    for (int m = 0; m < K4_CHUNK; m++)
        acc += Cp[m] * Vp[(size_t)m*DIM];
    atomicAdd(&out[b*DIM + d], acc);
}

// ---------------- launch -----------------------------------------------------
extern "C" void kernel_launch(void* const* d_in, const int* in_sizes, int n_in,
                              void* d_out, int out_size) {
    const float* x  = (const float*)d_in[0];
    const float* Wq = (const float*)d_in[1];
    const float* bq = (const float*)d_in[2];
    const float* Wk = (const float*)d_in[3];
    const float* bk = (const float*)d_in[4];
    const float* Wv = (const float*)d_in[5];
    const float* bv = (const float*)d_in[6];
    float* out = (float*)d_out;

    const int smem = 2 * BM * PADK * sizeof(float);   // 135168 bytes
    cudaFuncSetAttribute(proj_kernel,  cudaFuncAttributeMaxDynamicSharedMemorySize, smem);
    cudaFuncSetAttribute(score_kernel, cudaFuncAttributeMaxDynamicSharedMemorySize, smem);

    zero_kernel<<<(BATCH*SEQ + 255)/256, 256>>>(out);

    dim3 gProj(1, TOK/BM, 3);
    proj_kernel<<<gProj, 256, smem>>>(x, Wq, bq, Wk, bk, Wv, bv);

    dim3 gScore(SEQ/BN, SEQ/BM, BATCH);   // 32 x 32 x 4
    score_kernel<<<gScore, 256, smem>>>();

    dim3 gCol(SEQ/512, SEQ/K3_ROWS, BATCH);  // 8 x 16 x 4
    colsum_kernel<<<gCol, 256>>>();

    dim3 gOut(16, BATCH);
    out_kernel<<<gOut, 128>>>(out);
}

// round 4
// speedup vs baseline: 4.6180x; 2.0091x over previous
#include <cuda_runtime.h>
#include <cuda_bf16.h>
#include <math.h>
#include <stdint.h>

// Problem constants
#define BATCH 4
#define SEQ   4096
#define DIM   128
#define TOK   (BATCH*SEQ)   // 16384

// GEMM tiling
#define BM 128
#define BN 128
#define PADK 132    // fp32 smem row pitch for proj (floats)
#define SB   136    // bf16 smem row pitch for score (272 bytes -> ldmatrix conflict-free)

// ---------------- device scratch (allocation-free: __device__ globals) -------
__device__ __nv_bfloat16 g_Qh[TOK*DIM];                // Q in bf16 (score operand)
__device__ __nv_bfloat16 g_Kh[TOK*DIM];                // K in bf16
__device__ float g_V[TOK*DIM];                         // V stays fp32 (feeds output)
__device__ float g_S[BATCH*SEQ];                       // row sums of exp(scores)
__device__ float g_C[BATCH*SEQ];                       // column weights (already /N)
__device__ __nv_bfloat16 g_E[(size_t)BATCH*SEQ*SEQ];   // exp(scores) bf16, 134 MB

// ---------------- helpers ----------------------------------------------------
__device__ __forceinline__ float tf32_round(float x) {
    uint32_t u;
    asm("cvt.rna.tf32.f32 %0, %1;" : "=r"(u) : "f"(x));
    return __uint_as_float(u);
}

#define MMA_TF32(C, A, B)                                                     \
  asm volatile("mma.sync.aligned.m16n8k8.row.col.f32.tf32.tf32.f32 "          \
    "{%0,%1,%2,%3}, {%4,%5,%6,%7}, {%8,%9}, {%0,%1,%2,%3};"                   \
    : "+f"((C)[0]), "+f"((C)[1]), "+f"((C)[2]), "+f"((C)[3])                  \
    : "r"((A)[0]), "r"((A)[1]), "r"((A)[2]), "r"((A)[3]),                     \
      "r"((B)[0]), "r"((B)[1]))

#define MMA_BF16(C, A, B0, B1)                                                \
  asm volatile("mma.sync.aligned.m16n8k16.row.col.f32.bf16.bf16.f32 "         \
    "{%0,%1,%2,%3}, {%4,%5,%6,%7}, {%8,%9}, {%0,%1,%2,%3};"                   \
    : "+f"((C)[0]), "+f"((C)[1]), "+f"((C)[2]), "+f"((C)[3])                  \
    : "r"((A)[0]), "r"((A)[1]), "r"((A)[2]), "r"((A)[3]),                     \
      "r"(B0), "r"(B1))

#define LDMX4(R, ADDR)                                                        \
  asm volatile("ldmatrix.sync.aligned.m8n8.x4.shared.b16 {%0,%1,%2,%3}, [%4];"\
    : "=r"((R)[0]), "=r"((R)[1]), "=r"((R)[2]), "=r"((R)[3]) : "r"(ADDR))

// ---------------- zero accumulators + output --------------------------------
__global__ void zero_kernel(float* out) {
    int i = blockIdx.x * blockDim.x + threadIdx.x;
    if (i < BATCH*SEQ) { g_S[i] = 0.0f; g_C[i] = 0.0f; }
    if (i < BATCH*DIM) out[i] = 0.0f;
}

// ---------------- K1: QKV projection  y = x @ W^T + b  (tf32 mma) ------------
// blockIdx.z: 0->Q(bf16 out), 1->K(bf16 out), 2->V(fp32 out).
__global__ __launch_bounds__(256, 1)
void proj_kernel(const float* __restrict__ x,
                 const float* __restrict__ Wq, const float* __restrict__ bq,
                 const float* __restrict__ Wk, const float* __restrict__ bk,
                 const float* __restrict__ Wv, const float* __restrict__ bv) {
    extern __shared__ float sm[];
    float* As = sm;              // [BM][PADK] x tile
    float* Bs = sm + BM*PADK;    // [BN][PADK] W

    const float* W; const float* bias;
    if (blockIdx.z == 0)      { W = Wq; bias = bq; }
    else if (blockIdx.z == 1) { W = Wk; bias = bk; }
    else                      { W = Wv; bias = bv; }

    const int rowBase = blockIdx.y * BM;
    const int tid = threadIdx.x;

    for (int i = tid*4; i < BM*DIM; i += 256*4) {
        int r = i >> 7, k = i & 127;
        float4 v = *(const float4*)(x + (size_t)(rowBase + r)*DIM + k);
        v.x = tf32_round(v.x); v.y = tf32_round(v.y);
        v.z = tf32_round(v.z); v.w = tf32_round(v.w);
        *(float4*)(As + r*PADK + k) = v;
        float4 w = *(const float4*)(W + i);
        w.x = tf32_round(w.x); w.y = tf32_round(w.y);
        w.z = tf32_round(w.z); w.w = tf32_round(w.w);
        *(float4*)(Bs + r*PADK + k) = w;
    }
    __syncthreads();

    const int lane = tid & 31, warp = tid >> 5;
    const int wm = (warp >> 1) * 32;
    const int wn = (warp & 1) * 64;
    const int g = lane >> 2, t = lane & 3;

    float c[2][8][4];
    #pragma unroll
    for (int mt = 0; mt < 2; mt++)
        #pragma unroll
        for (int nt = 0; nt < 8; nt++)
            #pragma unroll
            for (int j = 0; j < 4; j++) c[mt][nt][j] = 0.0f;

    #pragma unroll
    for (int kk = 0; kk < DIM/8; kk++) {
        const int kb = kk*8;
        uint32_t a[2][4], bb[8][2];
        #pragma unroll
        for (int mt = 0; mt < 2; mt++) {
            const float* p = As + (wm + mt*16 + g)*PADK + kb + t;
            a[mt][0] = __float_as_uint(p[0]);
            a[mt][1] = __float_as_uint(p[8*PADK]);
            a[mt][2] = __float_as_uint(p[4]);
            a[mt][3] = __float_as_uint(p[8*PADK + 4]);
        }
        #pragma unroll
        for (int nt = 0; nt < 8; nt++) {
            const float* p = Bs + (wn + nt*8 + g)*PADK + kb + t;
            bb[nt][0] = __float_as_uint(p[0]);
            bb[nt][1] = __float_as_uint(p[4]);
        }
        #pragma unroll
        for (int mt = 0; mt < 2; mt++)
            #pragma unroll
            for (int nt = 0; nt < 8; nt++)
                MMA_TF32(c[mt][nt], a[mt], bb[nt]);
    }

    // epilogue
    const bool isQK = (blockIdx.z < 2);
    __nv_bfloat16* oh = (blockIdx.z == 0) ? g_Qh : g_Kh;
    #pragma unroll
    for (int mt = 0; mt < 2; mt++) {
        const int r0 = rowBase + wm + mt*16 + g;
        #pragma unroll
        for (int nt = 0; nt < 8; nt++) {
            const int cn = wn + nt*8 + 2*t;
            float b0 = __ldg(&bias[cn]), b1 = __ldg(&bias[cn+1]);
            float v00 = c[mt][nt][0] + b0, v01 = c[mt][nt][1] + b1;
            float v10 = c[mt][nt][2] + b0, v11 = c[mt][nt][3] + b1;
            if (isQK) {
                *(__nv_bfloat162*)(oh + (size_t)r0*DIM + cn)     = __floats2bfloat162_rn(v00, v01);
                *(__nv_bfloat162*)(oh + (size_t)(r0+8)*DIM + cn) = __floats2bfloat162_rn(v10, v11);
            } else {
                *(float2*)(g_V + (size_t)r0*DIM + cn)     = make_float2(v00, v01);
                *(float2*)(g_V + (size_t)(r0+8)*DIM + cn) = make_float2(v10, v11);
            }
        }
    }
}

// ---------------- K2: E = exp(Q @ K^T) (bf16 mma + ldmatrix) -----------------
__global__ __launch_bounds__(256, 2)
void score_kernel() {
    extern __shared__ __nv_bfloat16 smh[];
    __nv_bfloat16* Qs = smh;            // [BM][SB]
    __nv_bfloat16* Ks = smh + BM*SB;    // [BN][SB]

    const int b = blockIdx.z;
    const int rowBase = blockIdx.y * BM;
    const int colBase = blockIdx.x * BN;
    const int tid = threadIdx.x;

    // fill tiles: 128 rows x 16 chunks of 16B each
    {
        const uint4* Qg = (const uint4*)(g_Qh + ((size_t)b*SEQ + rowBase)*DIM);
        const uint4* Kg = (const uint4*)(g_Kh + ((size_t)b*SEQ + colBase)*DIM);
        #pragma unroll
        for (int i = tid; i < BM*16; i += 256) {
            int r = i >> 4, ch = i & 15;
            *(uint4*)(Qs + r*SB + ch*8) = Qg[r*16 + ch];
            *(uint4*)(Ks + r*SB + ch*8) = Kg[r*16 + ch];
        }
    }
    __syncthreads();

    const int lane = tid & 31, warp = tid >> 5;
    const int wm = (warp >> 1) * 32;   // 0,32,64,96
    const int wn = (warp & 1) * 64;    // 0,64

    // ldmatrix lane addressing (halfword offsets within tile)
    const int aRow = wm + (lane & 15);
    const int aCol = (lane >> 4) << 3;
    uint32_t aAddr = (uint32_t)__cvta_generic_to_shared(Qs + aRow*SB + aCol);
    const int bRow = wn + (lane & 7) + ((lane >> 4) << 3);
    const int bCol = ((lane >> 3) & 1) << 3;
    uint32_t bAddr = (uint32_t)__cvta_generic_to_shared(Ks + bRow*SB + bCol);

    float c[2][8][4];
    #pragma unroll
    for (int mt = 0; mt < 2; mt++)
        #pragma unroll
        for (int nt = 0; nt < 8; nt++)
            #pragma unroll
            for (int j = 0; j < 4; j++) c[mt][nt][j] = 0.0f;

    #pragma unroll
    for (int kk = 0; kk < DIM/16; kk++) {
        uint32_t a[2][4], bb[4][4];
        #pragma unroll
        for (int mt = 0; mt < 2; mt++)
            LDMX4(a[mt], aAddr + (mt*16*SB)*2 + kk*32);
        #pragma unroll
        for (int ntp = 0; ntp < 4; ntp++)
            LDMX4(bb[ntp], bAddr + (ntp*16*SB)*2 + kk*32);
        #pragma unroll
        for (int mt = 0; mt < 2; mt++)
            #pragma unroll
            for (int nt = 0; nt < 8; nt++)
                MMA_BF16(c[mt][nt], a[mt], bb[nt>>1][(nt&1)*2], bb[nt>>1][(nt&1)*2+1]);
    }

    // epilogue: exp, store bf16 E, reduce row sums
    const int g = lane >> 2, t = lane & 3;
    #pragma unroll
    for (int mt = 0; mt < 2; mt++) {
        const int r0 = rowBase + wm + mt*16 + g;
        const int r1 = r0 + 8;
        float rs0 = 0.0f, rs1 = 0.0f;
        #pragma unroll
        for (int nt = 0; nt < 8; nt++) {
            const int cn = colBase + wn + nt*8 + 2*t;
            float e0 = __expf(c[mt][nt][0]);
            float e1 = __expf(c[mt][nt][1]);
            float e2 = __expf(c[mt][nt][2]);
            float e3 = __expf(c[mt][nt][3]);
            rs0 += e0 + e1;
            rs1 += e2 + e3;
            size_t base0 = ((size_t)b*SEQ + r0)*SEQ + cn;
            size_t base1 = ((size_t)b*SEQ + r1)*SEQ + cn;
            *(__nv_bfloat162*)(g_E + base0) = __floats2bfloat162_rn(e0, e1);
            *(__nv_bfloat162*)(g_E + base1) = __floats2bfloat162_rn(e2, e3);
        }
        #pragma unroll
        for (int o = 1; o <= 2; o <<= 1) {
            rs0 += __shfl_xor_sync(0xffffffffu, rs0, o);
            rs1 += __shfl_xor_sync(0xffffffffu, rs1, o);
        }
        if (t == 0) {
            atomicAdd(&g_S[b*SEQ + r0], rs0);
            atomicAdd(&g_S[b*SEQ + r1], rs1);
        }
    }
}

// ---------------- K3: c[m] = (1/N) * sum_n E[n,m]/S[n] -----------------------
#define K3_ROWS 256
__global__ __launch_bounds__(256, 8)
void colsum_kernel() {
    __shared__ float invS[K3_ROWS];
    const int b = blockIdx.z;
    const int mBase = blockIdx.x * 512;
    const int nBase = blockIdx.y * K3_ROWS;
    const int tid = threadIdx.x;

    if (tid < K3_ROWS) invS[tid] = 1.0f / g_S[b*SEQ + nBase + tid];
    __syncthreads();

    const __nv_bfloat162* Ep =
        (const __nv_bfloat162*)(g_E + ((size_t)b*SEQ + nBase)*SEQ) + (mBase >> 1) + tid;
    const size_t strideV2 = SEQ / 2;

    float a0 = 0.f, a1 = 0.f, b0 = 0.f, b1 = 0.f;
    #pragma unroll 8
    for (int n = 0; n < K3_ROWS; n += 2) {
        float2 v0 = __bfloat1622float2(Ep[(size_t)n * strideV2]);
        float2 v1 = __bfloat1622float2(Ep[(size_t)(n+1) * strideV2]);
        a0 += v0.x * invS[n];   a1 += v0.y * invS[n];
        b0 += v1.x * invS[n+1]; b1 += v1.y * invS[n+1];
    }
    const int m = mBase + tid*2;
    atomicAdd(&g_C[b*SEQ + m],     (a0 + b0) * (1.0f/SEQ));
    atomicAdd(&g_C[b*SEQ + m + 1], (a1 + b1) * (1.0f/SEQ));
}

// ---------------- K4: out[b,d] = sum_m c[m] * V[b,m,d] -----------------------
#define K4_CHUNK (SEQ/16)   // 256 rows per block
__global__ __launch_bounds__(128, 8)
void out_kernel(float* __restrict__ out) {
    const int b = blockIdx.y;
    const int mBase = blockIdx.x * K4_CHUNK;
    const int d = threadIdx.x;
    const float* Vp = g_V + ((size_t)b*SEQ + mBase)*DIM + d;
    const float* Cp = g_C + b*SEQ + mBase;
    float acc = 0.0f;
    #pragma unroll 8
    for (int m = 0; m < K4_CHUNK; m++)
        acc += Cp[m] * Vp[(size_t)m*DIM];
    atomicAdd(&out[b*DIM + d], acc);
}

// ---------------- launch -----------------------------------------------------
extern "C" void kernel_launch(void* const* d_in, const int* in_sizes, int n_in,
                              void* d_out, int out_size) {
    const float* x  = (const float*)d_in[0];
    const float* Wq = (const float*)d_in[1];
    const float* bq = (const float*)d_in[2];
    const float* Wk = (const float*)d_in[3];
    const float* bk = (const float*)d_in[4];
    const float* Wv = (const float*)d_in[5];
    const float* bv = (const float*)d_in[6];
    float* out = (float*)d_out;

    const int smemProj  = 2 * BM * PADK * sizeof(float);          // 135168 B
    const int smemScore = 2 * BM * SB * sizeof(__nv_bfloat16);    // 69632 B
    cudaFuncSetAttribute(proj_kernel,  cudaFuncAttributeMaxDynamicSharedMemorySize, smemProj);
    cudaFuncSetAttribute(score_kernel, cudaFuncAttributeMaxDynamicSharedMemorySize, smemScore);

    zero_kernel<<<(BATCH*SEQ + 255)/256, 256>>>(out);

    dim3 gProj(1, TOK/BM, 3);
    proj_kernel<<<gProj, 256, smemProj>>>(x, Wq, bq, Wk, bk, Wv, bv);

    dim3 gScore(SEQ/BN, SEQ/BM, BATCH);   // 32 x 32 x 4
    score_kernel<<<gScore, 256, smemScore>>>();

    dim3 gCol(SEQ/512, SEQ/K3_ROWS, BATCH);  // 8 x 16 x 4
    colsum_kernel<<<gCol, 256>>>();

    dim3 gOut(16, BATCH);
    out_kernel<<<gOut, 128>>>(out);
}